// round 12
// baseline (speedup 1.0000x reference)
#include <cuda_runtime.h>
#include <math.h>

#define NG 1708
#define NGV 427           // NG/4 exactly
#define NH 5
#define NB 16
#define NC 34
#define NM 128            // interpolation nodes per (b,h)
#define NSPLIT 8          // blocks per (b,h) in table stage
#define NODES_PB (NM / NSPLIT)    // 16 nodes per block
#define THR_PN 16                 // threads per node
#define SEG 107                   // ceil(NG/16)
#define TPB 256
#define NCH 7
#define JPC 244           // NG / 7 exactly
#define LOG2E 1.44269504088896340736f

// Scratch (no allocations allowed)
__device__ float g_hbuf[2][NB * NG];        // ping-pong hidden state
__device__ float g_k[NH * NB * NG];         // raw k = h*wk
__device__ float g_v[NH * NB * NG];         // v = h*wv
__device__ float g_a[NB * NG];              // head-summed attention out
__device__ float g_FR[NH * NB * NM * 2];    // (F, R) interleaved
__device__ unsigned g_rng3[3][NH * NB * 4]; // encoded kmin,kmax,qmin,qmax
__device__ float g_stats3[3][NB * 2];       // (sum a, sum a^2) per layer

__device__ __forceinline__ float ex2(float a) {
    float r; asm("ex2.approx.f32 %0, %1;" : "=f"(r) : "f"(a)); return r;
}
__device__ __forceinline__ float lg2(float a) {
    float r; asm("lg2.approx.f32 %0, %1;" : "=f"(r) : "f"(a)); return r;
}
// order-preserving float<->unsigned encoding (unsigned compare == float compare)
__device__ __forceinline__ unsigned fenc(float f) {
    unsigned u = __float_as_uint(f);
    return (u & 0x80000000u) ? ~u : (u | 0x80000000u);
}
__device__ __forceinline__ float fdec(unsigned k) {
    unsigned u = (k & 0x80000000u) ? (k & 0x7FFFFFFFu) : ~k;
    return __uint_as_float(u);
}

// zero all per-replay accumulators (ranges + LN stats)
__global__ void init_kernel() {
    unsigned* r = &g_rng3[0][0];
    for (int i = threadIdx.x; i < 3 * NH * NB * 4; i += TPB)
        r[i] = ((i & 3) == 0 || (i & 3) == 2) ? 0xFFFFFFFFu : 0u;  // min:max
    float* s = &g_stats3[0][0];
    for (int i = threadIdx.x; i < 3 * NB * 2; i += TPB) s[i] = 0.f;
}

// ---------------------------------------------------------------------------
// stage1: grid (NCH, NH, NB). Applies previous LN+residual inline (stats from
// interp2 atomics), computes raw k,v -> g_k/g_v, hidden -> ping-pong buffer,
// and k/q ranges via encoded atomicMin/Max (deterministic).
// ---------------------------------------------------------------------------
__global__ __launch_bounds__(TPB) void stage1_kernel(
    const float* __restrict__ x, int L,
    const float* __restrict__ WQ, const float* __restrict__ WK,
    const float* __restrict__ WV,
    const float* __restrict__ ln_a, const float* __restrict__ ln_b)
{
    __shared__ float sred[32];
    const int chunk = blockIdx.x, h = blockIdx.y, b = blockIdx.z;
    const int idx = h * NB + b;
    const int tid = threadIdx.x;
    const int j = chunk * JPC + tid;
    const bool ok = (tid < JPC);
    const int pin  = 0 + (L == 2);       // L1 reads buf0, L2 reads buf1
    const int pout = (L == 1) ? 1 : 0;   // L0->0, L1->1, L2->0

    float kmx = -3.4e38f, kmn = 3.4e38f, qmx = -3.4e38f, qmn = 3.4e38f;
    if (ok) {
        float hv;
        if (L == 0) {
            hv = x[b * NG + j];
        } else {
            float S = g_stats3[L - 1][b * 2], SS = g_stats3[L - 1][b * 2 + 1];
            float mean = S / (float)NG;
            float var = (SS - (float)NG * mean * mean) / (float)(NG - 1);
            var = fmaxf(var, 0.f);
            float inv = 1.f / (sqrtf(var) + 1e-6f);
            float a = g_a[b * NG + j];
            hv = g_hbuf[pin][b * NG + j]
               + fmaf(ln_a[j] * (a - mean), inv, ln_b[j]);
        }
        float k = hv * WK[h * NG + j];
        float v = hv * WV[h * NG + j];
        float q = hv * WQ[h * NG + j] * LOG2E;
        g_k[idx * NG + j] = k;
        g_v[idx * NG + j] = v;
        if (h == 0) g_hbuf[pout][b * NG + j] = hv;
        kmx = k; kmn = k; qmx = q; qmn = q;
    }
    #pragma unroll
    for (int o = 16; o; o >>= 1) {
        kmx = fmaxf(kmx, __shfl_xor_sync(0xffffffffu, kmx, o));
        kmn = fminf(kmn, __shfl_xor_sync(0xffffffffu, kmn, o));
        qmx = fmaxf(qmx, __shfl_xor_sync(0xffffffffu, qmx, o));
        qmn = fminf(qmn, __shfl_xor_sync(0xffffffffu, qmn, o));
    }
    const int w = tid >> 5;
    if ((tid & 31) == 0) {
        sred[w] = kmx; sred[8 + w] = kmn;
        sred[16 + w] = qmx; sred[24 + w] = qmn;
    }
    __syncthreads();
    if (tid == 0) {
        float KM = sred[0], Km = sred[8], QM = sred[16], Qm = sred[24];
        #pragma unroll
        for (int i = 1; i < 8; i++) {
            KM = fmaxf(KM, sred[i]);      Km = fminf(Km, sred[8 + i]);
            QM = fmaxf(QM, sred[16 + i]); Qm = fminf(Qm, sred[24 + i]);
        }
        unsigned* r = &g_rng3[L][idx * 4];
        atomicMin(&r[0], fenc(Km));
        atomicMax(&r[1], fenc(KM));
        atomicMin(&r[2], fenc(Qm));
        atomicMax(&r[3], fenc(QM));
    }
}

// ---------------------------------------------------------------------------
// table: grid (NSPLIT, NH, NB); 16 nodes x 16 threads. Params derived inline
// from range words. bias = t*c + |t|*halfr keeps every ex2 arg <= 0.
// F stored in centered-k space: F(q) = log2 sum_j 2^{q*(k_j - c)}.
// ---------------------------------------------------------------------------
__global__ __launch_bounds__(TPB) void table_kernel(int L)
{
    __shared__ __align__(16) float sk[NG];
    __shared__ __align__(16) float sv[NG];
    const int chunk = blockIdx.x, h = blockIdx.y, b = blockIdx.z;
    const int idx = h * NB + b;
    const int tid = threadIdx.x;

    const unsigned* __restrict__ r = &g_rng3[L][idx * 4];
    const float Km = fdec(r[0]), KM = fdec(r[1]);
    const float Qm = fdec(r[2]), QM = fdec(r[3]);
    const float c = 0.5f * (KM + Km);
    const float halfr = 0.5f * (KM - Km);
    const float dq = fmaxf((QM - Qm) / (float)(NM - 1), 1e-12f);

    const float4* __restrict__ gk4 = reinterpret_cast<const float4*>(g_k + idx * NG);
    const float4* __restrict__ gv4 = reinterpret_cast<const float4*>(g_v + idx * NG);
    float4* __restrict__ sk4 = reinterpret_cast<float4*>(sk);
    float4* __restrict__ sv4 = reinterpret_cast<float4*>(sv);
    for (int j = tid; j < NGV; j += TPB) {
        sk4[j] = gk4[j];
        sv4[j] = gv4[j];
    }
    __syncthreads();

    const int m = chunk * NODES_PB + (tid >> 4);
    const int rr = tid & (THR_PN - 1);
    const float t = Qm + (float)m * dq;
    const float s = fabsf(t) * halfr;
    const float bias = t * c + s;              // arg = t*k_j - bias <= 0
    float f = 0.f, g = 0.f;
    const int j0 = rr * SEG;
    const int j1 = min(j0 + SEG, NG);
    #pragma unroll 4
    for (int j = j0; j < j1; j++) {
        float e = ex2(fmaf(t, sk[j], -bias));
        f += e;
        g = fmaf(e, sv[j], g);
    }
    #pragma unroll
    for (int o = 1; o < THR_PN; o <<= 1) {
        f += __shfl_xor_sync(0xffffffffu, f, o);
        g += __shfl_xor_sync(0xffffffffu, g, o);
    }
    if (rr == 0) {
        g_FR[(idx * NM + m) * 2]     = s + lg2(f);   // f in [1, NG]
        g_FR[(idx * NM + m) * 2 + 1] = g / f;
    }
}

// ---------------------------------------------------------------------------
// interp2: grid (NCH, NB). Per row i, all heads: cubic-interp F,R, exact
// diagonal, head-sum -> g_a; block-reduced LN stats -> per-layer atomics.
// ---------------------------------------------------------------------------
__global__ __launch_bounds__(TPB) void interp2_kernel(
    int L, const float* __restrict__ WQ, const float* __restrict__ W0)
{
    __shared__ float sprm[NH][3];   // q2min, invdq, c
    __shared__ float sred[16];
    const int b = blockIdx.y;
    const int i = blockIdx.x * TPB + threadIdx.x;
    const int tid = threadIdx.x;
    const bool ok = (i < NG);
    const int pout = (L == 1) ? 1 : 0;

    if (tid < NH) {
        const unsigned* r = &g_rng3[L][(tid * NB + b) * 4];
        float Km = fdec(r[0]), KM = fdec(r[1]);
        float Qm = fdec(r[2]), QM = fdec(r[3]);
        float dq = fmaxf((QM - Qm) / (float)(NM - 1), 1e-12f);
        sprm[tid][0] = Qm;
        sprm[tid][1] = 1.f / dq;
        sprm[tid][2] = 0.5f * (KM + Km);
    }
    __syncthreads();

    float a = 0.f;
    if (ok) {
        const float hv = g_hbuf[pout][b * NG + i];
        #pragma unroll
        for (int h = 0; h < NH; h++) {
            const int idx = h * NB + b;
            const float q2 = hv * WQ[h * NG + i] * LOG2E;
            const float kt = g_k[idx * NG + i] - sprm[h][2];
            const float v  = g_v[idx * NG + i];

            float u = (q2 - sprm[h][0]) * sprm[h][1];
            int j0 = (int)floorf(u);
            j0 = min(max(j0, 1), NM - 3);
            float ww = u - (float)j0;
            float aa = ww + 1.f, bb = ww - 1.f, cc = ww - 2.f;
            float wm1 = -ww * bb * cc * (1.f / 6.f);
            float w0  = aa * bb * cc * 0.5f;
            float w1  = -aa * ww * cc * 0.5f;
            float w2  = aa * ww * bb * (1.f / 6.f);

            const float2* __restrict__ FRp =
                reinterpret_cast<const float2*>(g_FR) + idx * NM + (j0 - 1);
            float2 p0 = FRp[0], p1 = FRp[1], p2 = FRp[2], p3 = FRp[3];
            float F = wm1 * p0.x + w0 * p1.x + w1 * p2.x + w2 * p3.x;
            float R = wm1 * p0.y + w0 * p1.y + w1 * p2.y + w2 * p3.y;

            float ed = ex2(fmaf(q2, kt, -F));   // e_i / f
            a = fmaf(W0[h], R - ed * v, a);
        }
        g_a[b * NG + i] = a;
    }

    float s = ok ? a : 0.f;
    float ss = ok ? a * a : 0.f;
    #pragma unroll
    for (int o = 16; o; o >>= 1) {
        s  += __shfl_xor_sync(0xffffffffu, s,  o);
        ss += __shfl_xor_sync(0xffffffffu, ss, o);
    }
    const int w = tid >> 5;
    if ((tid & 31) == 0) { sred[w] = s; sred[8 + w] = ss; }
    __syncthreads();
    if (tid == 0) {
        float S = 0.f, SS = 0.f;
        #pragma unroll
        for (int k = 0; k < 8; k++) { S += sred[k]; SS += sred[8 + k]; }
        atomicAdd(&g_stats3[L][b * 2], S);
        atomicAdd(&g_stats3[L][b * 2 + 1], SS);
    }
}

// ---------------------------------------------------------------------------
// final: apply layer-3 LN+residual (stats precomputed), FC, log_softmax.
// ---------------------------------------------------------------------------
__global__ __launch_bounds__(1024) void final_kernel(
    const float* __restrict__ ln_a, const float* __restrict__ ln_b,
    const float* __restrict__ fc_w, const float* __restrict__ fc_b,
    float* __restrict__ out)
{
    __shared__ float4 sa4[NGV];
    __shared__ float slog[NC];
    __shared__ float s_ls;
    const int b = blockIdx.x, tid = threadIdx.x;
    const int w = tid >> 5, l = tid & 31;

    float S = g_stats3[2][b * 2], SS = g_stats3[2][b * 2 + 1];
    float mean = S / (float)NG;
    float var = (SS - (float)NG * mean * mean) / (float)(NG - 1);
    var = fmaxf(var, 0.f);
    float inv = 1.f / (sqrtf(var) + 1e-6f);

    if (tid < NGV) {
        float4 a  = reinterpret_cast<const float4*>(g_a + b * NG)[tid];
        float4 bs = reinterpret_cast<const float4*>(&g_hbuf[0][b * NG])[tid];
        float4 la = reinterpret_cast<const float4*>(ln_a)[tid];
        float4 lb = reinterpret_cast<const float4*>(ln_b)[tid];
        float4 o;
        o.x = bs.x + fmaf(la.x * (a.x - mean), inv, lb.x);
        o.y = bs.y + fmaf(la.y * (a.y - mean), inv, lb.y);
        o.z = bs.z + fmaf(la.z * (a.z - mean), inv, lb.z);
        o.w = bs.w + fmaf(la.w * (a.w - mean), inv, lb.w);
        sa4[tid] = o;
    }
    __syncthreads();

    for (int c = w; c < NC; c += 32) {
        const float4* __restrict__ wr =
            reinterpret_cast<const float4*>(fc_w + c * NG);
        float d = 0.f;
        for (int j = l; j < NGV; j += 32) {
            float4 a = sa4[j], q = wr[j];
            d = fmaf(a.x, q.x, d); d = fmaf(a.y, q.y, d);
            d = fmaf(a.z, q.z, d); d = fmaf(a.w, q.w, d);
        }
        #pragma unroll
        for (int o = 16; o; o >>= 1) d += __shfl_xor_sync(0xffffffffu, d, o);
        if (l == 0) slog[c] = d + fc_b[c];
    }
    __syncthreads();
    if (tid == 0) {
        float M = slog[0];
        #pragma unroll
        for (int c = 1; c < NC; c++) M = fmaxf(M, slog[c]);
        float sum = 0.f;
        for (int c = 0; c < NC; c++) sum += expf(slog[c] - M);
        s_ls = M + logf(sum);
    }
    __syncthreads();
    if (tid < NC) out[b * NC + tid] = slog[tid] - s_ls;
}

extern "C" void kernel_launch(void* const* d_in, const int* in_sizes, int n_in,
                              void* d_out, int out_size) {
    const float* x    = (const float*)d_in[0];
    const float* WQ[3] = {(const float*)d_in[1], (const float*)d_in[5], (const float*)d_in[9]};
    const float* WK[3] = {(const float*)d_in[2], (const float*)d_in[6], (const float*)d_in[10]};
    const float* WV[3] = {(const float*)d_in[3], (const float*)d_in[7], (const float*)d_in[11]};
    const float* W0[3] = {(const float*)d_in[4], (const float*)d_in[8], (const float*)d_in[12]};
    const float* ln_a = (const float*)d_in[13];
    const float* ln_b = (const float*)d_in[14];
    const float* fc_w = (const float*)d_in[15];
    const float* fc_b = (const float*)d_in[16];

    init_kernel<<<1, TPB>>>();
    for (int L = 0; L < 3; L++) {
        stage1_kernel<<<dim3(NCH, NH, NB), TPB>>>(x, L, WQ[L], WK[L], WV[L],
                                                  ln_a, ln_b);
        table_kernel<<<dim3(NSPLIT, NH, NB), TPB>>>(L);
        interp2_kernel<<<dim3(NCH, NB), TPB>>>(L, WQ[L], W0[L]);
    }
    final_kernel<<<NB, 1024>>>(ln_a, ln_b, fc_w, fc_b, (float*)d_out);
}

// round 13
// speedup vs baseline: 1.7189x; 1.7189x over previous
#include <cuda_runtime.h>
#include <math.h>

#define NG 1708
#define NGV 427           // NG/4 exactly
#define NH 5
#define NB 16
#define NC 34
#define NM 128            // interpolation nodes per (b,h)
#define NSPLIT 8          // blocks per (b,h) in table stage
#define NODES_PB (NM / NSPLIT)    // 16 nodes per block
#define THR_PN 16                 // threads per node
#define SEGV 27                   // float4s per thread (thread 15 gets 22)
#define TPB 256

// Scratch (no allocations allowed)
__device__ float g_h[NB * NG];
__device__ float g_part[NH * NB * NG];
__device__ float g_F[NH * NB * NM];     // log2 of f(q) at nodes (shifted-k space)
__device__ float g_R[NH * NB * NM];     // r(q) = g/f at nodes
__device__ float g_prm[NH * NB * 4];    // c, q2min, dq, inv_dq

__device__ __forceinline__ float ex2(float a) {
    float r; asm("ex2.approx.f32 %0, %1;" : "=f"(r) : "f"(a)); return r;
}
__device__ __forceinline__ float lg2(float a) {
    float r; asm("lg2.approx.f32 %0, %1;" : "=f"(r) : "f"(a)); return r;
}

#define LOG2E 1.44269504088896340736f

// ---------------------------------------------------------------------------
// Table kernel: per (b,h), sample F(q)=log2 sum_j 2^{q*kt_j} and
// r(q) = sum_j 2^{q*kt_j} v_j / f at NM nodes over the actual q2 range.
// kt = k - c (c = midrange) is exactly softmax-invariant; per-node shift
// s=|t|*halfr makes every ex2 arg <= 0 (overflow impossible, f in [1, NG]).
// grid: (NSPLIT, NH, NB); block 256 = 16 nodes x 16 threads.
// Fully float4-vectorized: body does 0.5 LDS-issue/element (LDS.128).
// ---------------------------------------------------------------------------
__global__ __launch_bounds__(TPB) void table_kernel(
    const float* __restrict__ x, int use_x,
    const float* __restrict__ WQ, const float* __restrict__ WK,
    const float* __restrict__ WV)
{
    __shared__ __align__(16) float sk[NG];
    __shared__ __align__(16) float sv[NG];
    __shared__ float sred[32];
    __shared__ float sp[4];   // c, halfr, q2min, dq
    const int chunk = blockIdx.x, h = blockIdx.y, b = blockIdx.z;
    const int idx = h * NB + b;
    const int tid = threadIdx.x;
    const float4* __restrict__ hr4 =
        reinterpret_cast<const float4*>((use_x ? x : g_h) + b * NG);
    const float4* __restrict__ wq4 = reinterpret_cast<const float4*>(WQ + h * NG);
    const float4* __restrict__ wk4 = reinterpret_cast<const float4*>(WK + h * NG);
    const float4* __restrict__ wv4 = reinterpret_cast<const float4*>(WV + h * NG);
    float4* __restrict__ sk4 = reinterpret_cast<float4*>(sk);
    float4* __restrict__ sv4 = reinterpret_cast<float4*>(sv);

    float kmax = -3.4e38f, kmin = 3.4e38f, qmax = -3.4e38f, qmin = 3.4e38f;
    for (int j = tid; j < NGV; j += TPB) {      // 2 vector iterations
        float4 hv = hr4[j], wq_ = wq4[j], wk_ = wk4[j], wv_ = wv4[j];
        float4 k, v, q;
        k.x = hv.x * wk_.x; k.y = hv.y * wk_.y;
        k.z = hv.z * wk_.z; k.w = hv.w * wk_.w;
        v.x = hv.x * wv_.x; v.y = hv.y * wv_.y;
        v.z = hv.z * wv_.z; v.w = hv.w * wv_.w;
        q.x = hv.x * wq_.x * LOG2E; q.y = hv.y * wq_.y * LOG2E;
        q.z = hv.z * wq_.z * LOG2E; q.w = hv.w * wq_.w * LOG2E;
        sk4[j] = k; sv4[j] = v;
        kmax = fmaxf(kmax, fmaxf(fmaxf(k.x, k.y), fmaxf(k.z, k.w)));
        kmin = fminf(kmin, fminf(fminf(k.x, k.y), fminf(k.z, k.w)));
        qmax = fmaxf(qmax, fmaxf(fmaxf(q.x, q.y), fmaxf(q.z, q.w)));
        qmin = fminf(qmin, fminf(fminf(q.x, q.y), fminf(q.z, q.w)));
    }
    #pragma unroll
    for (int o = 16; o; o >>= 1) {
        kmax = fmaxf(kmax, __shfl_xor_sync(0xffffffffu, kmax, o));
        kmin = fminf(kmin, __shfl_xor_sync(0xffffffffu, kmin, o));
        qmax = fmaxf(qmax, __shfl_xor_sync(0xffffffffu, qmax, o));
        qmin = fminf(qmin, __shfl_xor_sync(0xffffffffu, qmin, o));
    }
    const int w = tid >> 5;
    if ((tid & 31) == 0) {
        sred[w] = kmax; sred[8 + w] = kmin;
        sred[16 + w] = qmax; sred[24 + w] = qmin;
    }
    __syncthreads();
    if (tid == 0) {
        float KM = sred[0], Km = sred[8], QM = sred[16], Qm = sred[24];
        #pragma unroll
        for (int i = 1; i < 8; i++) {
            KM = fmaxf(KM, sred[i]);      Km = fminf(Km, sred[8 + i]);
            QM = fmaxf(QM, sred[16 + i]); Qm = fminf(Qm, sred[24 + i]);
        }
        float c = 0.5f * (KM + Km);
        float halfr = 0.5f * (KM - Km);
        float dq = fmaxf((QM - Qm) / (float)(NM - 1), 1e-12f);
        sp[0] = c; sp[1] = halfr; sp[2] = Qm; sp[3] = dq;
        if (chunk == 0) {
            g_prm[idx * 4 + 0] = c;
            g_prm[idx * 4 + 1] = Qm;
            g_prm[idx * 4 + 2] = dq;
            g_prm[idx * 4 + 3] = 1.f / dq;
        }
    }
    __syncthreads();
    const float c = sp[0], halfr = sp[1], q2min = sp[2], dq = sp[3];

    // 16 nodes per block; node m handled by 16 threads, 27 float4s each
    const int m = chunk * NODES_PB + (tid >> 4);
    const int rr = tid & (THR_PN - 1);
    const float t = q2min + (float)m * dq;
    const float s = fabsf(t) * halfr;          // >= t*(k_j - c) for all j
    const float bias = t * c + s;              // arg = t*k_j - bias <= 0
    float f0 = 0.f, f1 = 0.f, g0 = 0.f, g1 = 0.f;
    const int v0 = rr * SEGV;
    const int v1 = min(v0 + SEGV, NGV);
    #pragma unroll 2
    for (int jv = v0; jv < v1; jv++) {
        float4 k4 = sk4[jv];
        float4 v4 = sv4[jv];
        float e0 = ex2(fmaf(t, k4.x, -bias));
        float e1 = ex2(fmaf(t, k4.y, -bias));
        float e2 = ex2(fmaf(t, k4.z, -bias));
        float e3 = ex2(fmaf(t, k4.w, -bias));
        f0 += e0; g0 = fmaf(e0, v4.x, g0);
        f1 += e1; g1 = fmaf(e1, v4.y, g1);
        f0 += e2; g0 = fmaf(e2, v4.z, g0);
        f1 += e3; g1 = fmaf(e3, v4.w, g1);
    }
    float f = f0 + f1, g = g0 + g1;
    #pragma unroll
    for (int o = 1; o < THR_PN; o <<= 1) {
        f += __shfl_xor_sync(0xffffffffu, f, o);
        g += __shfl_xor_sync(0xffffffffu, g, o);
    }
    if (rr == 0) {
        g_F[idx * NM + m] = s + lg2(f);        // f >= 1 always
        g_R[idx * NM + m] = g / f;
    }
}

// ---------------------------------------------------------------------------
// Interp kernel: per row i, cubic-Lagrange interpolate F and r at q2_i,
// subtract exact diagonal: out = r(q) - 2^(q*kt_i - F(q)) * v_i.
// grid: (7, NH, NB), block 256.
// ---------------------------------------------------------------------------
__global__ __launch_bounds__(TPB) void interp_kernel(
    const float* __restrict__ x, int use_x,
    const float* __restrict__ WQ, const float* __restrict__ WK,
    const float* __restrict__ WV)
{
    const int h = blockIdx.y, b = blockIdx.z;
    const int idx = h * NB + b;
    const int i = blockIdx.x * TPB + threadIdx.x;
    if (i >= NG) return;
    const float* __restrict__ hr = (use_x ? x : g_h) + b * NG;

    const float c     = g_prm[idx * 4 + 0];
    const float q2min = g_prm[idx * 4 + 1];
    const float invdq = g_prm[idx * 4 + 3];

    float hv = hr[i];
    float q2 = hv * (WQ + h * NG)[i] * LOG2E;
    float kt = hv * (WK + h * NG)[i] - c;
    float v  = hv * (WV + h * NG)[i];

    float u = (q2 - q2min) * invdq;
    int j0 = (int)floorf(u);
    j0 = min(max(j0, 1), NM - 3);
    float ww = u - (float)j0;

    // Lagrange cubic weights at offset ww for nodes {-1,0,1,2}
    float a = ww + 1.f, bb = ww - 1.f, cc = ww - 2.f;
    float wm1 = -ww * bb * cc * (1.f / 6.f);
    float w0  = a * bb * cc * 0.5f;
    float w1  = -a * ww * cc * 0.5f;
    float w2  = a * ww * bb * (1.f / 6.f);

    const float* __restrict__ Fp = g_F + idx * NM + (j0 - 1);
    const float* __restrict__ Rp = g_R + idx * NM + (j0 - 1);
    float F = wm1 * Fp[0] + w0 * Fp[1] + w1 * Fp[2] + w2 * Fp[3];
    float R = wm1 * Rp[0] + w0 * Rp[1] + w1 * Rp[2] + w2 * Rp[3];

    float ed_over_f = ex2(fmaf(q2, kt, -F));   // e_i / f, <= ~1 by construction
    g_part[idx * NG + i] = R - ed_over_f * v;
}

// ---------------------------------------------------------------------------
// ln_fc: verbatim from the passing R4/R10 kernel.
// ---------------------------------------------------------------------------
__global__ __launch_bounds__(1024) void ln_fc_kernel(
    const float* __restrict__ x, int use_x,
    const float* __restrict__ W0, const float* __restrict__ ln_a,
    const float* __restrict__ ln_b, int do_fc,
    const float* __restrict__ fc_w, const float* __restrict__ fc_b,
    float* __restrict__ out)
{
    __shared__ float4 sa4[NGV];
    __shared__ float sred[64];
    __shared__ float sb[2];
    __shared__ float slog[NC];
    __shared__ float s_ls;
    const int b = blockIdx.x, tid = threadIdx.x;
    const int w = tid >> 5, l = tid & 31;
    const float4* __restrict__ base4 =
        reinterpret_cast<const float4*>((use_x ? x : g_h) + b * NG);

    float w0[NH];
    #pragma unroll
    for (int h = 0; h < NH; h++) w0[h] = W0[h];

    float s = 0.f, ss = 0.f;
    if (tid < NGV) {
        float4 a = make_float4(0.f, 0.f, 0.f, 0.f);
        #pragma unroll
        for (int h = 0; h < NH; h++) {
            float4 p = reinterpret_cast<const float4*>(
                g_part + (h * NB + b) * NG)[tid];
            a.x = fmaf(w0[h], p.x, a.x);
            a.y = fmaf(w0[h], p.y, a.y);
            a.z = fmaf(w0[h], p.z, a.z);
            a.w = fmaf(w0[h], p.w, a.w);
        }
        sa4[tid] = a;
        s = (a.x + a.y) + (a.z + a.w);
        ss = fmaf(a.x, a.x, fmaf(a.y, a.y, fmaf(a.z, a.z, a.w * a.w)));
    }
    #pragma unroll
    for (int o = 16; o; o >>= 1) {
        s  += __shfl_xor_sync(0xffffffffu, s,  o);
        ss += __shfl_xor_sync(0xffffffffu, ss, o);
    }
    if (l == 0) { sred[w] = s; sred[32 + w] = ss; }
    __syncthreads();
    if (tid == 0) {
        float S = 0.f, SS = 0.f;
        #pragma unroll
        for (int i = 0; i < 32; i++) { S += sred[i]; SS += sred[32 + i]; }
        float mean = S / (float)NG;
        float var = (SS - (float)NG * mean * mean) / (float)(NG - 1);
        var = fmaxf(var, 0.f);
        sb[0] = mean;
        sb[1] = 1.f / (sqrtf(var) + 1e-6f);
    }
    __syncthreads();
    const float mean = sb[0], inv = sb[1];

    if (tid < NGV) {
        float4 a = sa4[tid];
        float4 bs = base4[tid];
        float4 la = reinterpret_cast<const float4*>(ln_a)[tid];
        float4 lb = reinterpret_cast<const float4*>(ln_b)[tid];
        float4 o;
        o.x = bs.x + fmaf(la.x * (a.x - mean), inv, lb.x);
        o.y = bs.y + fmaf(la.y * (a.y - mean), inv, lb.y);
        o.z = bs.z + fmaf(la.z * (a.z - mean), inv, lb.z);
        o.w = bs.w + fmaf(la.w * (a.w - mean), inv, lb.w);
        reinterpret_cast<float4*>(g_h + b * NG)[tid] = o;
        sa4[tid] = o;                       // keep h3 row for fused FC
    }

    if (!do_fc) return;
    __syncthreads();

    for (int c = w; c < NC; c += 32) {
        const float4* __restrict__ wr =
            reinterpret_cast<const float4*>(fc_w + c * NG);
        float d = 0.f;
        for (int j = l; j < NGV; j += 32) {
            float4 a = sa4[j], q = wr[j];
            d = fmaf(a.x, q.x, d); d = fmaf(a.y, q.y, d);
            d = fmaf(a.z, q.z, d); d = fmaf(a.w, q.w, d);
        }
        #pragma unroll
        for (int o = 16; o; o >>= 1) d += __shfl_xor_sync(0xffffffffu, d, o);
        if (l == 0) slog[c] = d + fc_b[c];
    }
    __syncthreads();
    if (tid == 0) {
        float M = slog[0];
        #pragma unroll
        for (int c = 1; c < NC; c++) M = fmaxf(M, slog[c]);
        float sum = 0.f;
        for (int c = 0; c < NC; c++) sum += expf(slog[c] - M);
        s_ls = M + logf(sum);
    }
    __syncthreads();
    if (tid < NC) out[b * NC + tid] = slog[tid] - s_ls;
}

extern "C" void kernel_launch(void* const* d_in, const int* in_sizes, int n_in,
                              void* d_out, int out_size) {
    const float* x    = (const float*)d_in[0];
    const float* WQ[3] = {(const float*)d_in[1], (const float*)d_in[5], (const float*)d_in[9]};
    const float* WK[3] = {(const float*)d_in[2], (const float*)d_in[6], (const float*)d_in[10]};
    const float* WV[3] = {(const float*)d_in[3], (const float*)d_in[7], (const float*)d_in[11]};
    const float* W0[3] = {(const float*)d_in[4], (const float*)d_in[8], (const float*)d_in[12]};
    const float* ln_a = (const float*)d_in[13];
    const float* ln_b = (const float*)d_in[14];
    const float* fc_w = (const float*)d_in[15];
    const float* fc_b = (const float*)d_in[16];

    for (int L = 0; L < 3; L++) {
        int ux = (L == 0) ? 1 : 0;
        table_kernel<<<dim3(NSPLIT, NH, NB), TPB>>>(x, ux, WQ[L], WK[L], WV[L]);
        interp_kernel<<<dim3(7, NH, NB), TPB>>>(x, ux, WQ[L], WK[L], WV[L]);
        ln_fc_kernel<<<NB, 1024>>>(x, ux, W0[L], ln_a, ln_b,
                                   L == 2 ? 1 : 0, fc_w, fc_b, (float*)d_out);
    }
}

// round 14
// speedup vs baseline: 1.8656x; 1.0853x over previous
#include <cuda_runtime.h>
#include <math.h>

#define NG 1708
#define NGV 427           // NG/4 exactly
#define NH 5
#define NB 16
#define NC 34
#define NM 128            // interpolation nodes per (b,h)
#define NSPLIT 8          // blocks per (b,h) in table stage
#define NODES_PB 16               // nodes per block
#define NSEG 64                   // segments (threads) sharing one node-group
#define SEGV 7                    // float4s per segment: 61*7 = 427 exactly
#define TPB 256

// Scratch (no allocations allowed)
__device__ float g_h[NB * NG];
__device__ float g_part[NH * NB * NG];
__device__ float g_F[NH * NB * NM];     // log2 of f(q) at nodes (shifted-k space)
__device__ float g_R[NH * NB * NM];     // r(q) = g/f at nodes
__device__ float g_prm[NH * NB * 4];    // c, q2min, dq, inv_dq

__device__ __forceinline__ float ex2(float a) {
    float r; asm("ex2.approx.f32 %0, %1;" : "=f"(r) : "f"(a)); return r;
}
__device__ __forceinline__ float lg2(float a) {
    float r; asm("lg2.approx.f32 %0, %1;" : "=f"(r) : "f"(a)); return r;
}

#define LOG2E 1.44269504088896340736f

// ---------------------------------------------------------------------------
// Table kernel: per (b,h), sample F(q)=log2 sum_j 2^{q*kt_j} and
// r(q) = sum e*v/f at NM nodes over the actual q2 range. kt = k - c
// (midrange; exactly softmax-invariant); per-node shift s=|t|*halfr makes
// every ex2 arg <= 0 (no overflow, f in [1, NG]).
// grid (NSPLIT, NH, NB); block 256 = 4 node-groups x 64 segments.
// Each thread loads its k4/v4 segment ONCE and evaluates 4 nodes -> smem
// traffic = 2 B/element (4x less than 1-node-per-thread mapping).
// ---------------------------------------------------------------------------
__global__ __launch_bounds__(TPB) void table_kernel(
    const float* __restrict__ x, int use_x,
    const float* __restrict__ WQ, const float* __restrict__ WK,
    const float* __restrict__ WV)
{
    __shared__ __align__(16) float sk[NG];
    __shared__ __align__(16) float sv[NG];
    __shared__ float sred[32];
    __shared__ float sp[4];          // c, halfr, q2min, dq
    __shared__ float sfg[8][8];      // per-warp partials: f[4], g[4]
    const int chunk = blockIdx.x, h = blockIdx.y, b = blockIdx.z;
    const int idx = h * NB + b;
    const int tid = threadIdx.x;
    const float4* __restrict__ hr4 =
        reinterpret_cast<const float4*>((use_x ? x : g_h) + b * NG);
    const float4* __restrict__ wq4 = reinterpret_cast<const float4*>(WQ + h * NG);
    const float4* __restrict__ wk4 = reinterpret_cast<const float4*>(WK + h * NG);
    const float4* __restrict__ wv4 = reinterpret_cast<const float4*>(WV + h * NG);
    float4* __restrict__ sk4 = reinterpret_cast<float4*>(sk);
    float4* __restrict__ sv4 = reinterpret_cast<float4*>(sv);

    float kmax = -3.4e38f, kmin = 3.4e38f, qmax = -3.4e38f, qmin = 3.4e38f;
    for (int j = tid; j < NGV; j += TPB) {      // 2 vector iterations
        float4 hv = hr4[j], wq_ = wq4[j], wk_ = wk4[j], wv_ = wv4[j];
        float4 k, v, q;
        k.x = hv.x * wk_.x; k.y = hv.y * wk_.y;
        k.z = hv.z * wk_.z; k.w = hv.w * wk_.w;
        v.x = hv.x * wv_.x; v.y = hv.y * wv_.y;
        v.z = hv.z * wv_.z; v.w = hv.w * wv_.w;
        q.x = hv.x * wq_.x * LOG2E; q.y = hv.y * wq_.y * LOG2E;
        q.z = hv.z * wq_.z * LOG2E; q.w = hv.w * wq_.w * LOG2E;
        sk4[j] = k; sv4[j] = v;
        kmax = fmaxf(kmax, fmaxf(fmaxf(k.x, k.y), fmaxf(k.z, k.w)));
        kmin = fminf(kmin, fminf(fminf(k.x, k.y), fminf(k.z, k.w)));
        qmax = fmaxf(qmax, fmaxf(fmaxf(q.x, q.y), fmaxf(q.z, q.w)));
        qmin = fminf(qmin, fminf(fminf(q.x, q.y), fminf(q.z, q.w)));
    }
    #pragma unroll
    for (int o = 16; o; o >>= 1) {
        kmax = fmaxf(kmax, __shfl_xor_sync(0xffffffffu, kmax, o));
        kmin = fminf(kmin, __shfl_xor_sync(0xffffffffu, kmin, o));
        qmax = fmaxf(qmax, __shfl_xor_sync(0xffffffffu, qmax, o));
        qmin = fminf(qmin, __shfl_xor_sync(0xffffffffu, qmin, o));
    }
    const int w = tid >> 5;
    if ((tid & 31) == 0) {
        sred[w] = kmax; sred[8 + w] = kmin;
        sred[16 + w] = qmax; sred[24 + w] = qmin;
    }
    __syncthreads();
    if (tid == 0) {
        float KM = sred[0], Km = sred[8], QM = sred[16], Qm = sred[24];
        #pragma unroll
        for (int i = 1; i < 8; i++) {
            KM = fmaxf(KM, sred[i]);      Km = fminf(Km, sred[8 + i]);
            QM = fmaxf(QM, sred[16 + i]); Qm = fminf(Qm, sred[24 + i]);
        }
        float c = 0.5f * (KM + Km);
        float halfr = 0.5f * (KM - Km);
        float dq = fmaxf((QM - Qm) / (float)(NM - 1), 1e-12f);
        sp[0] = c; sp[1] = halfr; sp[2] = Qm; sp[3] = dq;
        if (chunk == 0) {
            g_prm[idx * 4 + 0] = c;
            g_prm[idx * 4 + 1] = Qm;
            g_prm[idx * 4 + 2] = dq;
            g_prm[idx * 4 + 3] = 1.f / dq;
        }
    }
    __syncthreads();
    const float c = sp[0], halfr = sp[1], q2min = sp[2], dq = sp[3];

    // node-group ng = tid>>6 (constant per warp-pair); segment = tid & 63
    const int ng = tid >> 6;
    const int seg = tid & (NSEG - 1);
    const int mbase = chunk * NODES_PB + ng * 4;
    float t[4], bias[4], f[4], g[4];
    #pragma unroll
    for (int n = 0; n < 4; n++) {
        t[n] = q2min + (float)(mbase + n) * dq;
        bias[n] = t[n] * c + fabsf(t[n]) * halfr;   // arg = t*k - bias <= 0
        f[n] = 0.f; g[n] = 0.f;
    }
    const int v0 = seg * SEGV;
    const int v1 = min(v0 + SEGV, NGV);             // segs 0..60 full, 61+ empty
    for (int jv = v0; jv < v1; jv++) {
        float4 k4 = sk4[jv];
        float4 v4 = sv4[jv];
        #pragma unroll
        for (int n = 0; n < 4; n++) {
            float e0 = ex2(fmaf(t[n], k4.x, -bias[n]));
            float e1 = ex2(fmaf(t[n], k4.y, -bias[n]));
            float e2 = ex2(fmaf(t[n], k4.z, -bias[n]));
            float e3 = ex2(fmaf(t[n], k4.w, -bias[n]));
            f[n] += (e0 + e1) + (e2 + e3);
            g[n] = fmaf(e0, v4.x, fmaf(e1, v4.y, fmaf(e2, v4.z, fmaf(e3, v4.w, g[n]))));
        }
    }
    #pragma unroll
    for (int o = 16; o; o >>= 1) {
        #pragma unroll
        for (int n = 0; n < 4; n++) {
            f[n] += __shfl_xor_sync(0xffffffffu, f[n], o);
            g[n] += __shfl_xor_sync(0xffffffffu, g[n], o);
        }
    }
    if ((tid & 31) == 0) {
        #pragma unroll
        for (int n = 0; n < 4; n++) { sfg[w][n] = f[n]; sfg[w][4 + n] = g[n]; }
    }
    __syncthreads();
    if (tid < NODES_PB) {                 // tid = ng2*4 + n
        const int ng2 = tid >> 2, n = tid & 3;
        float ff = sfg[2 * ng2][n]     + sfg[2 * ng2 + 1][n];
        float gg = sfg[2 * ng2][4 + n] + sfg[2 * ng2 + 1][4 + n];
        const int m = chunk * NODES_PB + tid;
        const float tt = q2min + (float)m * dq;
        const float ss = fabsf(tt) * halfr;
        g_F[idx * NM + m] = ss + lg2(ff);       // ff >= 1 always
        g_R[idx * NM + m] = gg / ff;
    }
}

// ---------------------------------------------------------------------------
// Interp kernel: per row i, cubic-Lagrange interpolate F and r at q2_i,
// subtract exact diagonal: out = r(q) - 2^(q*kt_i - F(q)) * v_i.
// grid: (7, NH, NB), block 256.
// ---------------------------------------------------------------------------
__global__ __launch_bounds__(TPB) void interp_kernel(
    const float* __restrict__ x, int use_x,
    const float* __restrict__ WQ, const float* __restrict__ WK,
    const float* __restrict__ WV)
{
    const int h = blockIdx.y, b = blockIdx.z;
    const int idx = h * NB + b;
    const int i = blockIdx.x * TPB + threadIdx.x;
    if (i >= NG) return;
    const float* __restrict__ hr = (use_x ? x : g_h) + b * NG;

    const float c     = g_prm[idx * 4 + 0];
    const float q2min = g_prm[idx * 4 + 1];
    const float invdq = g_prm[idx * 4 + 3];

    float hv = hr[i];
    float q2 = hv * (WQ + h * NG)[i] * LOG2E;
    float kt = hv * (WK + h * NG)[i] - c;
    float v  = hv * (WV + h * NG)[i];

    float u = (q2 - q2min) * invdq;
    int j0 = (int)floorf(u);
    j0 = min(max(j0, 1), NM - 3);
    float ww = u - (float)j0;

    // Lagrange cubic weights at offset ww for nodes {-1,0,1,2}
    float a = ww + 1.f, bb = ww - 1.f, cc = ww - 2.f;
    float wm1 = -ww * bb * cc * (1.f / 6.f);
    float w0  = a * bb * cc * 0.5f;
    float w1  = -a * ww * cc * 0.5f;
    float w2  = a * ww * bb * (1.f / 6.f);

    const float* __restrict__ Fp = g_F + idx * NM + (j0 - 1);
    const float* __restrict__ Rp = g_R + idx * NM + (j0 - 1);
    float F = wm1 * Fp[0] + w0 * Fp[1] + w1 * Fp[2] + w2 * Fp[3];
    float R = wm1 * Rp[0] + w0 * Rp[1] + w1 * Rp[2] + w2 * Rp[3];

    float ed_over_f = ex2(fmaf(q2, kt, -F));   // e_i / f, <= ~1 by construction
    g_part[idx * NG + i] = R - ed_over_f * v;
}

// ---------------------------------------------------------------------------
// ln_fc: verbatim from the passing R4/R10 kernel.
// ---------------------------------------------------------------------------
__global__ __launch_bounds__(1024) void ln_fc_kernel(
    const float* __restrict__ x, int use_x,
    const float* __restrict__ W0, const float* __restrict__ ln_a,
    const float* __restrict__ ln_b, int do_fc,
    const float* __restrict__ fc_w, const float* __restrict__ fc_b,
    float* __restrict__ out)
{
    __shared__ float4 sa4[NGV];
    __shared__ float sred[64];
    __shared__ float sb[2];
    __shared__ float slog[NC];
    __shared__ float s_ls;
    const int b = blockIdx.x, tid = threadIdx.x;
    const int w = tid >> 5, l = tid & 31;
    const float4* __restrict__ base4 =
        reinterpret_cast<const float4*>((use_x ? x : g_h) + b * NG);

    float w0[NH];
    #pragma unroll
    for (int h = 0; h < NH; h++) w0[h] = W0[h];

    float s = 0.f, ss = 0.f;
    if (tid < NGV) {
        float4 a = make_float4(0.f, 0.f, 0.f, 0.f);
        #pragma unroll
        for (int h = 0; h < NH; h++) {
            float4 p = reinterpret_cast<const float4*>(
                g_part + (h * NB + b) * NG)[tid];
            a.x = fmaf(w0[h], p.x, a.x);
            a.y = fmaf(w0[h], p.y, a.y);
            a.z = fmaf(w0[h], p.z, a.z);
            a.w = fmaf(w0[h], p.w, a.w);
        }
        sa4[tid] = a;
        s = (a.x + a.y) + (a.z + a.w);
        ss = fmaf(a.x, a.x, fmaf(a.y, a.y, fmaf(a.z, a.z, a.w * a.w)));
    }
    #pragma unroll
    for (int o = 16; o; o >>= 1) {
        s  += __shfl_xor_sync(0xffffffffu, s,  o);
        ss += __shfl_xor_sync(0xffffffffu, ss, o);
    }
    if (l == 0) { sred[w] = s; sred[32 + w] = ss; }
    __syncthreads();
    if (tid == 0) {
        float S = 0.f, SS = 0.f;
        #pragma unroll
        for (int i = 0; i < 32; i++) { S += sred[i]; SS += sred[32 + i]; }
        float mean = S / (float)NG;
        float var = (SS - (float)NG * mean * mean) / (float)(NG - 1);
        var = fmaxf(var, 0.f);
        sb[0] = mean;
        sb[1] = 1.f / (sqrtf(var) + 1e-6f);
    }
    __syncthreads();
    const float mean = sb[0], inv = sb[1];

    if (tid < NGV) {
        float4 a = sa4[tid];
        float4 bs = base4[tid];
        float4 la = reinterpret_cast<const float4*>(ln_a)[tid];
        float4 lb = reinterpret_cast<const float4*>(ln_b)[tid];
        float4 o;
        o.x = bs.x + fmaf(la.x * (a.x - mean), inv, lb.x);
        o.y = bs.y + fmaf(la.y * (a.y - mean), inv, lb.y);
        o.z = bs.z + fmaf(la.z * (a.z - mean), inv, lb.z);
        o.w = bs.w + fmaf(la.w * (a.w - mean), inv, lb.w);
        reinterpret_cast<float4*>(g_h + b * NG)[tid] = o;
        sa4[tid] = o;                       // keep h3 row for fused FC
    }

    if (!do_fc) return;
    __syncthreads();

    for (int c = w; c < NC; c += 32) {
        const float4* __restrict__ wr =
            reinterpret_cast<const float4*>(fc_w + c * NG);
        float d = 0.f;
        for (int j = l; j < NGV; j += 32) {
            float4 a = sa4[j], q = wr[j];
            d = fmaf(a.x, q.x, d); d = fmaf(a.y, q.y, d);
            d = fmaf(a.z, q.z, d); d = fmaf(a.w, q.w, d);
        }
        #pragma unroll
        for (int o = 16; o; o >>= 1) d += __shfl_xor_sync(0xffffffffu, d, o);
        if (l == 0) slog[c] = d + fc_b[c];
    }
    __syncthreads();
    if (tid == 0) {
        float M = slog[0];
        #pragma unroll
        for (int c = 1; c < NC; c++) M = fmaxf(M, slog[c]);
        float sum = 0.f;
        for (int c = 0; c < NC; c++) sum += expf(slog[c] - M);
        s_ls = M + logf(sum);
    }
    __syncthreads();
    if (tid < NC) out[b * NC + tid] = slog[tid] - s_ls;
}

extern "C" void kernel_launch(void* const* d_in, const int* in_sizes, int n_in,
                              void* d_out, int out_size) {
    const float* x    = (const float*)d_in[0];
    const float* WQ[3] = {(const float*)d_in[1], (const float*)d_in[5], (const float*)d_in[9]};
    const float* WK[3] = {(const float*)d_in[2], (const float*)d_in[6], (const float*)d_in[10]};
    const float* WV[3] = {(const float*)d_in[3], (const float*)d_in[7], (const float*)d_in[11]};
    const float* W0[3] = {(const float*)d_in[4], (const float*)d_in[8], (const float*)d_in[12]};
    const float* ln_a = (const float*)d_in[13];
    const float* ln_b = (const float*)d_in[14];
    const float* fc_w = (const float*)d_in[15];
    const float* fc_b = (const float*)d_in[16];

    for (int L = 0; L < 3; L++) {
        int ux = (L == 0) ? 1 : 0;
        table_kernel<<<dim3(NSPLIT, NH, NB), TPB>>>(x, ux, WQ[L], WK[L], WV[L]);
        interp_kernel<<<dim3(7, NH, NB), TPB>>>(x, ux, WQ[L], WK[L], WV[L]);
        ln_fc_kernel<<<NB, 1024>>>(x, ux, W0[L], ln_a, ln_b,
                                   L == 2 ? 1 : 0, fc_w, fc_b, (float*)d_out);
    }
}